// round 17
// baseline (speedup 1.0000x reference)
#include <cuda_runtime.h>
#include <cuda_fp16.h>
#include <cstdint>
#include <math.h>

#define Bsz 8192
#define Hdim 1024
#define G4 4096
#define HG (1024 * 4096)

#define BM 128      // batch rows per CTA
#define BN 128      // permuted z-cols per CTA (= 32 units x 4 gates)
#define BK 64       // K per pipeline chunk (4 k16-steps)
#define NCHUNK (Hdim / BK)   // 16
#define NSTAGE 3
#define NTH 256

#define STAGE_BYTES 32768    // A: 16KB swizzled + B: 16KB swizzled
#define STB_OFF 16384
#define MBAR_OFF (NSTAGE * STAGE_BYTES)
#define SMEM_TOTAL (NSTAGE * STAGE_BYTES + 2048)   // align pad + mbars

// ---------------- device scratch (allocation-free) ----------------
// g_W: B in STAGED-BLOCK layout: 16KB block per [l][bx(32)][c(16)]
__device__ __align__(256) __half g_W[4ull * HG];
// h buffers in STAGED-BLOCK layout: 16KB block per [by(64)][c(16)]
__device__ __align__(256) __half g_h0s[Bsz * Hdim];
__device__ __align__(256) __half g_has[Bsz * Hdim];
__device__ __align__(256) __half g_hbs[Bsz * Hdim];
__device__ float  g_ca[Bsz * Hdim];
__device__ float  g_cb[Bsz * Hdim];
__device__ float  g_biasp[4 * G4];       // permuted biases per layer
__device__ float  g_wx0p[G4];            // permuted Wx0

// permuted column layout: n' = (u>>2)*16 + (gate>>1)*8 + (u&3)*2 + (gate&1)
__device__ __forceinline__ int np_to_col(int np) {
    int u = ((np >> 4) << 2) | ((np >> 1) & 3);
    int gate = (((np >> 3) & 1) << 1) | (np & 1);
    return gate * 1024 + u;
}
__device__ __forceinline__ uint32_t smem_u32(const void* p) {
    uint32_t a;
    asm("{ .reg .u64 t; cvta.to.shared.u64 t, %1; cvt.u32.u64 %0, t; }" : "=r"(a) : "l"(p));
    return a;
}
__device__ __forceinline__ float sigm(float z) { return 1.0f / (1.0f + __expf(-z)); }
__device__ __forceinline__ float tanha(float x) {
    float r; asm("tanh.approx.f32 %0, %1;" : "=f"(r) : "f"(x)); return r;
}

#define MBAR_INIT(a, n) \
    asm volatile("mbarrier.init.shared.b64 [%0], %1;" :: "r"(a), "r"((uint32_t)(n)) : "memory")
#define MBAR_EXPECT(a, b) \
    asm volatile("mbarrier.arrive.expect_tx.shared.b64 _, [%0], %1;" :: "r"(a), "r"((uint32_t)(b)) : "memory")
#define MBAR_ARRIVE(a) \
    asm volatile("mbarrier.arrive.shared.b64 _, [%0];" :: "r"(a) : "memory")
#define BULKCP(dst, src, n, mb)                                               \
    asm volatile("cp.async.bulk.shared::cluster.global.mbarrier::complete_tx::bytes " \
                 "[%0], [%1], %2, [%3];"                                      \
                 :: "r"(dst), "l"(src), "r"((uint32_t)(n)), "r"(mb) : "memory")
#define MBAR_WAIT(a, par) do {                                                    \
    asm volatile(                                                                 \
        "{\n\t.reg .pred P1;\n\t"                                                 \
        "WL%=:\n\t"                                                               \
        "mbarrier.try_wait.parity.acquire.cta.shared::cta.b64 P1, [%0], %1, 0x989680;\n\t" \
        "@P1 bra.uni WD%=;\n\t"                                                   \
        "bra.uni WL%=;\n\t"                                                       \
        "WD%=:\n\t}"                                                              \
        :: "r"(a), "r"((uint32_t)(par)) : "memory");                              \
} while (0)

#define LDSM4(r0, r1, r2, r3, a)                                              \
    asm volatile("ldmatrix.sync.aligned.m8n8.x4.shared.b16 {%0,%1,%2,%3}, [%4];" \
                 : "=r"(r0), "=r"(r1), "=r"(r2), "=r"(r3) : "r"(a))
#define LDSM4T(r0, r1, r2, r3, a)                                             \
    asm volatile("ldmatrix.sync.aligned.m8n8.x4.trans.shared.b16 {%0,%1,%2,%3}, [%4];" \
                 : "=r"(r0), "=r"(r1), "=r"(r2), "=r"(r3) : "r"(a))

// fp16-accumulator mma: D,C in 2 regs (half2 x2)
#define MMAH(d, a, b0_, b1_)                                                  \
    asm volatile(                                                             \
        "mma.sync.aligned.m16n8k16.row.col.f16.f16.f16.f16 "                  \
        "{%0,%1}, {%2,%3,%4,%5}, {%6,%7}, {%0,%1};\n"                         \
        : "+r"((d)[0]), "+r"((d)[1])                                          \
        : "r"((a)[0]), "r"((a)[1]), "r"((a)[2]), "r"((a)[3]),                 \
          "r"(b0_), "r"(b1_))

// ---------------- prep kernels (identical to R14) ----------------
__global__ void wprep_kernel(const float4* __restrict__ Wh0,
                             const float4* __restrict__ Wx,
                             const float4* __restrict__ Wh) {
    size_t idx = (size_t)blockIdx.x * blockDim.x + threadIdx.x;  // < 4*1024*256
    int u4 = (int)(idx & 255);
    size_t kl = idx >> 8;             // l*1024 + k
    int l = (int)(kl >> 10);
    int k = (int)(kl & 1023);
    __half out[16];
    #pragma unroll
    for (int gate = 0; gate < 4; gate++) {
        size_t col4 = (size_t)(gate * 1024 + u4 * 4) >> 2;
        float4 v;
        if (l == 0) {
            v = Wh0[(size_t)k * 1024 + col4];
        } else {
            size_t o = (size_t)(l - 1) * (HG / 4) + (size_t)k * 1024 + col4;
            float4 a = Wx[o], b = Wh[o];
            v.x = a.x + b.x; v.y = a.y + b.y; v.z = a.z + b.z; v.w = a.w + b.w;
        }
        int base = ((gate >> 1) << 3) | (gate & 1);
        out[base + 0] = __float2half_rn(v.x);
        out[base + 2] = __float2half_rn(v.y);
        out[base + 4] = __float2half_rn(v.z);
        out[base + 6] = __float2half_rn(v.w);
    }
    int c = k >> 6, kr = k & 63;
    #pragma unroll
    for (int j = 0; j < 2; j++) {
        int n16 = u4 * 2 + j;
        int bx = n16 >> 4, nn = n16 & 15;
        size_t half_off = (((size_t)l * 32 + bx) * 16 + c) * 8192
                          + kr * 128 + 8 * (nn ^ (kr & 7));
        *(uint4*)(g_W + half_off) = ((const uint4*)out)[j];
    }
}
__global__ void hprep_kernel(const float4* __restrict__ h0) {
    size_t idx = (size_t)blockIdx.x * blockDim.x + threadIdx.x;  // < Bsz*128
    int row = (int)(idx >> 7);
    int k16 = (int)(idx & 127);
    float4 v0 = h0[(size_t)row * 256 + k16 * 2];
    float4 v1 = h0[(size_t)row * 256 + k16 * 2 + 1];
    __half out[8];
    out[0] = __float2half_rn(v0.x); out[1] = __float2half_rn(v0.y);
    out[2] = __float2half_rn(v0.z); out[3] = __float2half_rn(v0.w);
    out[4] = __float2half_rn(v1.x); out[5] = __float2half_rn(v1.y);
    out[6] = __float2half_rn(v1.z); out[7] = __float2half_rn(v1.w);
    int blk = (row >> 7) * 16 + (k16 >> 3);
    int r = row & 127, kk = k16 & 7;
    size_t half_off = (size_t)blk * 8192 + r * 64 + 8 * (kk ^ (r & 7));
    *(uint4*)(g_h0s + half_off) = *(const uint4*)out;
}
__global__ void bprep_kernel(const float* __restrict__ b0,
                             const float* __restrict__ bb,
                             const float* __restrict__ Wx0) {
    int idx = blockIdx.x * blockDim.x + threadIdx.x;   // < 5*4096
    int np = idx & 4095;
    int l = idx >> 12;
    int col = np_to_col(np);
    if (l < 4) {
        g_biasp[idx] = (l == 0) ? b0[col] : bb[(l - 1) * G4 + col];
    } else {
        g_wx0p[np] = Wx0[col];
    }
}

// -- fused LSTM layer: bulk-copy staging + free-running warps (R14 core) ----
// -- NEW: fp16-accumulator mma with K=32 windows promoted to fp32 masters --
__global__ void __launch_bounds__(NTH, 2)
lstm_layer_kernel(int layer,
                  const float* __restrict__ xvec,
                  const float* __restrict__ c0ext,
                  float* __restrict__ dout)
{
    const __half *A;
    const float *c_in;
    float *c_out;
    __half *h_out_h;      // staged layout (layers 0-2)
    float *h_out_f;       // fp32 row-major (layer 3)
    if (layer == 0) {
        A = g_h0s; c_in = c0ext;
        c_out = g_ca; h_out_h = g_has; h_out_f = nullptr;
    } else if (layer == 1) {
        A = g_has; c_in = g_ca;
        c_out = g_cb; h_out_h = g_hbs; h_out_f = nullptr;
    } else if (layer == 2) {
        A = g_hbs; c_in = g_cb;
        c_out = g_ca; h_out_h = g_has; h_out_f = nullptr;
    } else {
        A = g_has; c_in = g_ca;
        c_out = dout; h_out_h = nullptr; h_out_f = dout + (size_t)Bsz * Hdim;
    }
    const bool is_l0 = (layer == 0);
    const float* biasp = g_biasp + layer * G4;

    extern __shared__ char smem_raw[];
    const uint32_t sb = (smem_u32(smem_raw) + 1023u) & ~1023u;  // 1024-align
    const int tid  = threadIdx.x;
    const int lane = tid & 31;
    const int wid  = tid >> 5;
    const int wm   = wid >> 2;        // 0..1  (64 m rows each)
    const int wn   = wid & 3;         // 0..3  (32 n' cols each)
    const int rowBase = blockIdx.y * BM;
    const int nBase   = blockIdx.x * BN;

    const char* AsrcBase = (const char*)A + (size_t)blockIdx.y * 16 * 16384;
    const char* BsrcBase = (const char*)g_W
        + (((size_t)layer * 32 + blockIdx.x) * 16) * 16384;

    // mbarriers: full[s] (count 1, tx); empty[s] (count 8)
    if (tid == 0) {
        #pragma unroll
        for (int s = 0; s < NSTAGE; s++) {
            MBAR_INIT(sb + MBAR_OFF + s * 8, 1);
            MBAR_INIT(sb + MBAR_OFF + 24 + s * 8, 8);
        }
    }
    __syncthreads();

    auto issue_chunk = [&](int c) {
        const int s = c % NSTAGE;
        const uint32_t mb = sb + MBAR_OFF + s * 8;
        const uint32_t st = sb + s * STAGE_BYTES;
        MBAR_EXPECT(mb, STAGE_BYTES);
        BULKCP(st, AsrcBase + (size_t)c * 16384, 16384, mb);
        BULKCP(st + STB_OFF, BsrcBase + (size_t)c * 16384, 16384, mb);
    };

    float acc[4][4][4];
    #pragma unroll
    for (int mt = 0; mt < 4; mt++)
        #pragma unroll
        for (int j = 0; j < 4; j++)
            #pragma unroll
            for (int r = 0; r < 4; r++) acc[mt][j][r] = 0.0f;

    // per-lane ldmatrix base-address components (ks=0)
    const int arow = wm * 64 + (lane & 15);              // per mt: +mt*16
    const int ahi  = lane >> 4;                          // 0/1 (k-half unit)
    const int bm   = lane >> 3;                          // matrix id 0..3
    const int br   = lane & 7;                           // row within 8
    const int bkoff = br + (bm & 1) * 8;                 // k row offset within 16
    const int bnunit = wn * 4 + (bm >> 1);               // n' 16B-unit

    uint32_t offA[4], offB[2];
    #pragma unroll
    for (int mt = 0; mt < 4; mt++) {
        int rr = arow + mt * 16;
        offA[mt] = (uint32_t)(rr * 128 + 16 * (ahi ^ (rr & 7)));
    }
    #pragma unroll
    for (int jp = 0; jp < 2; jp++)
        offB[jp] = (uint32_t)(bkoff * 256 + 16 * ((bnunit + jp * 2) ^ (bkoff & 7)));

    // prologue: issue all 3 stages
    if (tid == 0) {
        issue_chunk(0);
        issue_chunk(1);
        issue_chunk(2);
    }

    for (int c = 0; c < NCHUNK; c++) {
        const int s = c % NSTAGE;
        MBAR_WAIT(sb + MBAR_OFF + s * 8, (c / NSTAGE) & 1);
        const uint32_t stA = sb + s * STAGE_BYTES;
        const uint32_t stB = stA + STB_OFF;

        #pragma unroll
        for (int hf = 0; hf < 2; hf++) {           // two K=32 half-chunks
            // B fragments for ks = hf*2 + {0,1}, all 4 n-blocks
            uint32_t bfr[2][4][2];
            #pragma unroll
            for (int k2 = 0; k2 < 2; k2++) {
                const uint32_t boff = (uint32_t)((hf * 2 + k2) * 4096);
                uint32_t r0, r1, r2, r3;
                LDSM4T(r0, r1, r2, r3, stB + offB[0] + boff);
                bfr[k2][0][0] = r0; bfr[k2][0][1] = r1;
                bfr[k2][1][0] = r2; bfr[k2][1][1] = r3;
                LDSM4T(r0, r1, r2, r3, stB + offB[1] + boff);
                bfr[k2][2][0] = r0; bfr[k2][2][1] = r1;
                bfr[k2][3][0] = r2; bfr[k2][3][1] = r3;
            }
            #pragma unroll
            for (int mt = 0; mt < 4; mt++) {
                uint32_t afm[2][4];
                #pragma unroll
                for (int k2 = 0; k2 < 2; k2++) {
                    const uint32_t axor = (uint32_t)((hf * 2 + k2) << 5);
                    LDSM4(afm[k2][0], afm[k2][1], afm[k2][2], afm[k2][3],
                          (stA + offA[mt]) ^ axor);
                }
                #pragma unroll
                for (int jq = 0; jq < 2; jq++) {   // j pairs (2jq, 2jq+1)
                    uint32_t w0[2] = {0u, 0u}, w1[2] = {0u, 0u};
                    MMAH(w0, afm[0], bfr[0][jq * 2 + 0][0], bfr[0][jq * 2 + 0][1]);
                    MMAH(w1, afm[0], bfr[0][jq * 2 + 1][0], bfr[0][jq * 2 + 1][1]);
                    MMAH(w0, afm[1], bfr[1][jq * 2 + 0][0], bfr[1][jq * 2 + 0][1]);
                    MMAH(w1, afm[1], bfr[1][jq * 2 + 1][0], bfr[1][jq * 2 + 1][1]);
                    // promote fp16 windows -> fp32 masters
                    float2 p;
                    p = __half22float2(*(__half2*)&w0[0]);
                    acc[mt][jq * 2 + 0][0] += p.x; acc[mt][jq * 2 + 0][1] += p.y;
                    p = __half22float2(*(__half2*)&w0[1]);
                    acc[mt][jq * 2 + 0][2] += p.x; acc[mt][jq * 2 + 0][3] += p.y;
                    p = __half22float2(*(__half2*)&w1[0]);
                    acc[mt][jq * 2 + 1][0] += p.x; acc[mt][jq * 2 + 1][1] += p.y;
                    p = __half22float2(*(__half2*)&w1[1]);
                    acc[mt][jq * 2 + 1][2] += p.x; acc[mt][jq * 2 + 1][3] += p.y;
                }
            }
        }

        // stage s drained by this warp (all LDSMs consumed by mma above)
        if (lane == 0) MBAR_ARRIVE(sb + MBAR_OFF + 24 + s * 8);
        if (tid == 0 && c + 3 < NCHUNK) {
            MBAR_WAIT(sb + MBAR_OFF + 24 + s * 8, (c / NSTAGE) & 1);
            issue_chunk(c + 3);
        }
    }

    // ---- epilogue: gates + cell update; h written in staged layout ----
    const int a4 = lane & 3;
    #pragma unroll
    for (int mt = 0; mt < 4; mt++) {
        #pragma unroll
        for (int rh = 0; rh < 2; rh++) {
            const int row = rowBase + wm * 64 + mt * 16 + (lane >> 2) + rh * 8;
            const float xr = is_l0 ? xvec[row] : 0.0f;
            #pragma unroll
            for (int g16 = 0; g16 < 2; g16++) {
                const int nl = wn * 32 + g16 * 16 + a4 * 2;     // n' of gate0
                const int u  = blockIdx.x * 32 + wn * 8 + g16 * 4 + a4;
                float zi = acc[mt][g16 * 2 + 0][rh * 2 + 0] + biasp[nBase + nl];
                float zf = acc[mt][g16 * 2 + 0][rh * 2 + 1] + biasp[nBase + nl + 1];
                float zg = acc[mt][g16 * 2 + 1][rh * 2 + 0] + biasp[nBase + nl + 8];
                float zo = acc[mt][g16 * 2 + 1][rh * 2 + 1] + biasp[nBase + nl + 9];
                if (is_l0) {
                    zi += xr * g_wx0p[nBase + nl];
                    zf += xr * g_wx0p[nBase + nl + 1];
                    zg += xr * g_wx0p[nBase + nl + 8];
                    zo += xr * g_wx0p[nBase + nl + 9];
                }
                const float ig = sigm(zi);
                const float fg = sigm(zf);
                const float gg = tanha(zg);
                const float og = sigm(zo);
                const size_t off = (size_t)row * Hdim + u;
                const float cn = fg * c_in[off] + ig * gg;
                c_out[off] = cn;
                const float hv = og * tanha(cn);
                if (h_out_f) {
                    h_out_f[off] = hv;
                } else {
                    int blk = (row >> 7) * 16 + (u >> 6);
                    int r = row & 127, k16 = (u >> 3) & 7, kk = u & 7;
                    size_t hoff = (size_t)blk * 8192 + r * 64
                                  + 8 * (k16 ^ (r & 7)) + kk;
                    h_out_h[hoff] = __float2half_rn(hv);
                }
            }
        }
    }
}

// ---------------- prediction head ----------------
__global__ void head_kernel(const float* __restrict__ h,
                            const float* __restrict__ Wd,
                            const float* __restrict__ bd,
                            float* __restrict__ out)
{
    int warpg = (blockIdx.x * blockDim.x + threadIdx.x) >> 5;
    int lane = threadIdx.x & 31;
    const float4* hp = (const float4*)(h + (size_t)warpg * Hdim);
    const float4* wp = (const float4*)Wd;
    float s = 0.0f;
    #pragma unroll
    for (int i = 0; i < 8; i++) {
        float4 a = hp[lane + i * 32];
        float4 w = wp[lane + i * 32];
        s += a.x * w.x + a.y * w.y + a.z * w.z + a.w * w.w;
    }
    #pragma unroll
    for (int o = 16; o; o >>= 1) s += __shfl_xor_sync(0xffffffffu, s, o);
    if (lane == 0) out[warpg] = s + bd[0];
}

extern "C" void kernel_launch(void* const* d_in, const int* in_sizes, int n_in,
                              void* d_out, int out_size)
{
    const float* x   = (const float*)d_in[0];
    const float* c0  = (const float*)d_in[1];
    const float* h0  = (const float*)d_in[2];
    const float* Wx0 = (const float*)d_in[3];
    const float* Wh0 = (const float*)d_in[4];
    const float* b0  = (const float*)d_in[5];
    const float* Wx  = (const float*)d_in[6];
    const float* Wh  = (const float*)d_in[7];
    const float* bb  = (const float*)d_in[8];
    const float* Wd  = (const float*)d_in[9];
    const float* bd  = (const float*)d_in[10];
    float* out = (float*)d_out;  // [c | h | x_pred]

    cudaFuncSetAttribute(lstm_layer_kernel,
                         cudaFuncAttributeMaxDynamicSharedMemorySize, SMEM_TOTAL);

    wprep_kernel<<<(4 * 1024 * 256) / 256, 256>>>((const float4*)Wh0,
                                                  (const float4*)Wx,
                                                  (const float4*)Wh);
    hprep_kernel<<<(Bsz * 128) / 256, 256>>>((const float4*)h0);
    bprep_kernel<<<(5 * G4) / 256, 256>>>(b0, bb, Wx0);

    dim3 grid(G4 / BN, Bsz / BM);   // 32 x 64 = 2048 CTAs
    for (int l = 0; l < 4; l++)
        lstm_layer_kernel<<<grid, NTH, SMEM_TOTAL>>>(l, x, c0, out);

    head_kernel<<<Bsz / 8, 256>>>(out + (size_t)Bsz * Hdim, Wd, bd,
                                  out + 2ull * (size_t)Bsz * Hdim);
}